// round 12
// baseline (speedup 1.0000x reference)
#include <cuda_runtime.h>

// WavetableSynth: B=16, L=48000, W=64, LWT=512
// inputs: pitch (B*L f32), envelope (B*L f32), attention (B*L*W f32), wavetables (W*LWT f32)
// output: (B, L, 1) f32

#define BB 16
#define LL 48000
#define WW 64
#define LWT_ 512

static constexpr float K_INC = 512.0f / 16000.0f; // 0.032f in f32

#define NT1 3000   // 48000 / 16 tiles per row
#define NT2 188    // ceil(3000 / 16)
#define NT3 12     // ceil(188 / 16)

#define TPW 5                  // tiles per warp chunk (3000 = 600*5 exact)
#define SPW (TPW * 16)         // 80 samples per chunk
#define CHUNKS_PER_ROW 600
#define NCHUNKS (BB * CHUNKS_PER_ROW)   // 9600 = 300 CTAs * 32 warps

// scratch (referenced ONLY from device code)
__device__ float g_G1[BB * NT1];
__device__ float g_P3[BB * NT2];
__device__ float g_wtT[LWT_ * WW];   // transposed table [512][64], 256B rows

// ---------------------------------------------------------------------------
// K1: tile sums G1 (one thread per tile) — exact XLA op order.
// Idle-thread side job: transpose wavetables into g_wtT (32768 elements).
// ---------------------------------------------------------------------------
__global__ void __launch_bounds__(128) k1_tilesums(const float* __restrict__ pitch,
                                                   const float* __restrict__ wt) {
    int tid = blockIdx.x * blockDim.x + threadIdx.x;
    if (tid < LWT_ * WW) {
        int idx = tid >> 6, w = tid & 63;
        g_wtT[tid] = wt[w * LWT_ + idx];
    }
    if (tid >= BB * NT1) return;
    int b = tid / NT1, i = tid - b * NT1;
    const float4* q = (const float4*)(pitch + b * LL + i * 16);
    float4 v0 = q[0], v1 = q[1], v2 = q[2], v3 = q[3];
    float lv[16] = {v0.x,v0.y,v0.z,v0.w, v1.x,v1.y,v1.z,v1.w,
                    v2.x,v2.y,v2.z,v2.w, v3.x,v3.y,v3.z,v3.w};
    float acc = __fmul_rn(K_INC, lv[0]);
    #pragma unroll
    for (int j = 1; j < 16; j++) acc = __fadd_rn(acc, __fmul_rn(K_INC, lv[j]));
    g_G1[tid] = acc;
}

// ---------------------------------------------------------------------------
// K2: per batch row — G2, G3, P4 top scan, P3. Exact op order. Tiny.
// ---------------------------------------------------------------------------
__global__ void __launch_bounds__(192) k2_midscan() {
    __shared__ float G2[NT2], P4[NT3];
    const int b = blockIdx.x;
    const int t = threadIdx.x;
    const float* G1 = g_G1 + b * NT1;

    if (t < NT2) {
        int base = t * 16, end = min(base + 16, NT1);
        float acc = G1[base];
        for (int i = base + 1; i < end; i++) acc = __fadd_rn(acc, G1[i]);
        G2[t] = acc;
    }
    __syncthreads();
    if (t == 0) {
        float G3[NT3];
        for (int w = 0; w < NT3; w++) {
            int base = w * 16, end = min(base + 16, NT2);
            float acc = G2[base];
            for (int i = base + 1; i < end; i++) acc = __fadd_rn(acc, G2[i]);
            G3[w] = acc;
        }
        float acc = G3[0];
        P4[0] = acc;
        for (int w = 1; w < NT3; w++) { acc = __fadd_rn(acc, G3[w]); P4[w] = acc; }
    }
    __syncthreads();
    if (t < NT2) {
        int w = t >> 4, base = w * 16;
        float acc = G2[base];
        for (int i = base + 1; i <= t; i++) acc = __fadd_rn(acc, G2[i]);
        g_P3[b * NT2 + t] = (w > 0) ? __fadd_rn(P4[w - 1], acc) : acc;
    }
}

// ---------------------------------------------------------------------------
// synth: warp owns a 5-tile (80-sample) chunk. Table gathers hit the
// L1-resident transposed table via __ldg (no smem table => 2 CTAs/SM,
// 64 warps). Phase A computes r into smem (10KB/CTA only).
// ---------------------------------------------------------------------------
__global__ void __launch_bounds__(1024, 2) synth_kernel(
    const float*  __restrict__ pitch,
    const float*  __restrict__ env,
    const float4* __restrict__ att4,      // [B*L][16] float4
    float*        __restrict__ out)
{
    __shared__ float s_rbuf[32 * SPW];    // per-warp r values

    const int t    = threadIdx.x;
    const int lane = t & 31;
    const int wrp  = t >> 5;

    const int gwarp = blockIdx.x * 32 + wrp;   // chunk id, < NCHUNKS
    const int b  = gwarp / CHUNKS_PER_ROW;
    const int k  = gwarp - b * CHUNKS_PER_ROW;
    const int first_tile = k * TPW;
    const int s0 = b * LL + first_tile * 16;   // global first sample

    float* s_r = s_rbuf + wrp * SPW;

    // -------- Phase A: per-tile scans (lanes 0..4), exact k3 op order ------
    if (lane < TPW) {
        const int i = first_tile + lane;
        const float* p  = pitch + b * LL + i * 16;
        const float* p0 = pitch + i * 16;            // batch row 0
        const float* G1 = g_G1 + b * NT1;

        float pref = 0.0f;
        bool has_pref = (i > 0);
        if (has_pref) {
            int j = i - 1, u = j >> 4, base = u * 16;
            float acc = G1[base];
            for (int kk = base + 1; kk <= j; kk++) acc = __fadd_rn(acc, G1[kk]);
            pref = (u > 0) ? __fadd_rn(g_P3[b * NT2 + (u - 1)], acc) : acc;
        }

        float acc = 0.0f;
        #pragma unroll
        for (int j = 0; j < 16; j++) {
            float leaf = __fmul_rn(K_INC, p[j]);
            acc = (j == 0) ? leaf : __fadd_rn(acc, leaf);
            float cum = has_pref ? __fadd_rn(pref, acc) : acc;
            float x = fmaf(-K_INC, p0[j], cum);  // XLA: sub(cum, mul) -> fma
            float r = fmodf(x, 512.0f);
            if (r < 0.0f) r = __fadd_rn(r, 512.0f);
            if (__fsub_rn(512.0f, r) < 1e-5f) r = 0.0f;
            s_r[lane * 16 + j] = r;
        }
    }
    __syncwarp();

    // -------- Phase B: pair-of-quads loop with depth-1 prefetch --------
    const int grp = lane >> 3;             // sample within quad
    const int ls  = lane & 7;
    const int nq  = TPW * 4;               // 20 quads (even)

    float  e0_c, e1_c, r0_c, r1_c;
    float4 a00_c, a01_c, a10_c, a11_c;
    {
        int sA = s0 + grp, sB = s0 + 4 + grp;
        e0_c = env[sA];  e1_c = env[sB];
        r0_c = s_r[grp]; r1_c = s_r[4 + grp];
        const float4* apA = att4 + (size_t)sA * (WW / 4);
        const float4* apB = att4 + (size_t)sB * (WW / 4);
        a00_c = __ldcs(apA + ls);  a01_c = __ldcs(apA + ls + 8);
        a10_c = __ldcs(apB + ls);  a11_c = __ldcs(apB + ls + 8);
    }

    for (int q = 0; q < nq; q += 2) {
        // register prefetch for next pair
        float  e0_n = 0.0f, e1_n = 0.0f, r0_n = 0.0f, r1_n = 0.0f;
        float4 a00_n = {}, a01_n = {}, a10_n = {}, a11_n = {};
        if (q + 2 < nq) {
            int sA = s0 + 4 * (q + 2) + grp, sB = s0 + 4 * (q + 3) + grp;
            e0_n = env[sA];  e1_n = env[sB];
            r0_n = s_r[4 * (q + 2) + grp]; r1_n = s_r[4 * (q + 3) + grp];
            const float4* apA = att4 + (size_t)sA * (WW / 4);
            const float4* apB = att4 + (size_t)sB * (WW / 4);
            a00_n = __ldcs(apA + ls);  a01_n = __ldcs(apA + ls + 8);
            a10_n = __ldcs(apB + ls);  a11_n = __ldcs(apB + ls + 8);
        }

        // --- stream 0 (quad q): L1-resident table gathers ---
        float lowA = floorf(r0_c);
        float alA  = __fsub_rn(r0_c, lowA);
        int ilA = (int)lowA;
        int ihA = ((int)ceilf(r0_c)) & (LWT_ - 1);
        const float4* wlA = (const float4*)(g_wtT + ilA * WW);
        const float4* whA = (const float4*)(g_wtT + ihA * WW);
        float4 loA0 = __ldg(wlA + ls), loA1 = __ldg(wlA + ls + 8);
        float4 hiA0 = __ldg(whA + ls), hiA1 = __ldg(whA + ls + 8);

        // --- stream 1 (quad q+1) ---
        float lowB = floorf(r1_c);
        float alB  = __fsub_rn(r1_c, lowB);
        int ilB = (int)lowB;
        int ihB = ((int)ceilf(r1_c)) & (LWT_ - 1);
        const float4* wlB = (const float4*)(g_wtT + ilB * WW);
        const float4* whB = (const float4*)(g_wtT + ihB * WW);
        float4 loB0 = __ldg(wlB + ls), loB1 = __ldg(wlB + ls + 8);
        float4 hiB0 = __ldg(whB + ls), hiB1 = __ldg(whB + ls + 8);

        float accA;
        accA = a00_c.x * fmaf(alA, hiA0.x - loA0.x, loA0.x);
        accA = fmaf(a00_c.y, fmaf(alA, hiA0.y - loA0.y, loA0.y), accA);
        accA = fmaf(a00_c.z, fmaf(alA, hiA0.z - loA0.z, loA0.z), accA);
        accA = fmaf(a00_c.w, fmaf(alA, hiA0.w - loA0.w, loA0.w), accA);
        accA = fmaf(a01_c.x, fmaf(alA, hiA1.x - loA1.x, loA1.x), accA);
        accA = fmaf(a01_c.y, fmaf(alA, hiA1.y - loA1.y, loA1.y), accA);
        accA = fmaf(a01_c.z, fmaf(alA, hiA1.z - loA1.z, loA1.z), accA);
        accA = fmaf(a01_c.w, fmaf(alA, hiA1.w - loA1.w, loA1.w), accA);

        float accB;
        accB = a10_c.x * fmaf(alB, hiB0.x - loB0.x, loB0.x);
        accB = fmaf(a10_c.y, fmaf(alB, hiB0.y - loB0.y, loB0.y), accB);
        accB = fmaf(a10_c.z, fmaf(alB, hiB0.z - loB0.z, loB0.z), accB);
        accB = fmaf(a10_c.w, fmaf(alB, hiB0.w - loB0.w, loB0.w), accB);
        accB = fmaf(a11_c.x, fmaf(alB, hiB1.x - loB1.x, loB1.x), accB);
        accB = fmaf(a11_c.y, fmaf(alB, hiB1.y - loB1.y, loB1.y), accB);
        accB = fmaf(a11_c.z, fmaf(alB, hiB1.z - loB1.z, loB1.z), accB);
        accB = fmaf(a11_c.w, fmaf(alB, hiB1.w - loB1.w, loB1.w), accB);

        accA += __shfl_xor_sync(0xFFFFFFFFu, accA, 1);
        accB += __shfl_xor_sync(0xFFFFFFFFu, accB, 1);
        accA += __shfl_xor_sync(0xFFFFFFFFu, accA, 2);
        accB += __shfl_xor_sync(0xFFFFFFFFu, accB, 2);
        accA += __shfl_xor_sync(0xFFFFFFFFu, accA, 4);
        accB += __shfl_xor_sync(0xFFFFFFFFu, accB, 4);

        if (ls == 0) {
            out[s0 + 4 * q + grp]       = accA * e0_c;
            out[s0 + 4 * (q + 1) + grp] = accB * e1_c;
        }

        e0_c = e0_n; e1_c = e1_n; r0_c = r0_n; r1_c = r1_n;
        a00_c = a00_n; a01_c = a01_n; a10_c = a10_n; a11_c = a11_n;
    }
}

// ---------------------------------------------------------------------------
extern "C" void kernel_launch(void* const* d_in, const int* in_sizes, int n_in,
                              void* d_out, int out_size) {
    const float* pitch = (const float*)d_in[0];
    const float* env   = (const float*)d_in[1];
    const float* att   = (const float*)d_in[2];
    const float* wt    = (const float*)d_in[3];
    float* out         = (float*)d_out;

    k1_tilesums<<<(BB * NT1 + 127) / 128, 128>>>(pitch, wt);
    k2_midscan<<<BB, 192>>>();
    synth_kernel<<<NCHUNKS / 32, 1024>>>(pitch, env, (const float4*)att, out);
}

// round 13
// speedup vs baseline: 1.5267x; 1.5267x over previous
#include <cuda_runtime.h>

// WavetableSynth: B=16, L=48000, W=64, LWT=512
// inputs: pitch (B*L f32), envelope (B*L f32), attention (B*L*W f32), wavetables (W*LWT f32)
// output: (B, L, 1) f32

#define BB 16
#define LL 48000
#define WW 64
#define LWT_ 512

static constexpr float K_INC = 512.0f / 16000.0f; // 0.032f in f32

#define NT1 3000   // 48000 / 16 tiles per row
#define NT2 188    // ceil(3000 / 16)
#define NT3 12     // ceil(188 / 16)

// chunking: 296 chunks per row -> 16*296 = 4736 chunks = 148 CTAs exactly.
// chunks 0..39 have 11 tiles, chunks 40..295 have 10 tiles (40*11+256*10=3000)
#define CPR 296
#define NCHUNKS (BB * CPR)     // 4736
#define MAX_TPW 11
#define MAX_SPW (MAX_TPW * 16) // 176

// scratch (referenced ONLY from device code)
__device__ float g_G1[BB * NT1];
__device__ float g_P3[BB * NT2];

// ---------------------------------------------------------------------------
// scan_kernel: fused G1/G2/G3/P4/P3, one CTA per batch row (16 CTAs x 1024).
// Exact XLA radix-16 op order (identical to the round-6 fused version).
// ---------------------------------------------------------------------------
__global__ void __launch_bounds__(1024, 1) scan_kernel(const float* __restrict__ pitch) {
    __shared__ float sG1[NT1];
    __shared__ float sG2[NT2], sP4[NT3];
    const int b = blockIdx.x;
    const int t = threadIdx.x;
    const float* p = pitch + b * LL;

    for (int i = t; i < NT1; i += 1024) {
        const float4* q = (const float4*)(p + i * 16);
        float4 v0 = q[0], v1 = q[1], v2 = q[2], v3 = q[3];
        float lv[16] = {v0.x,v0.y,v0.z,v0.w, v1.x,v1.y,v1.z,v1.w,
                        v2.x,v2.y,v2.z,v2.w, v3.x,v3.y,v3.z,v3.w};
        float acc = __fmul_rn(K_INC, lv[0]);
        #pragma unroll
        for (int j = 1; j < 16; j++) acc = __fadd_rn(acc, __fmul_rn(K_INC, lv[j]));
        sG1[i] = acc;
        g_G1[b * NT1 + i] = acc;
    }
    __syncthreads();

    if (t < NT2) {
        int base = t * 16, end = min(base + 16, NT1);
        float acc = sG1[base];
        for (int i = base + 1; i < end; i++) acc = __fadd_rn(acc, sG1[i]);
        sG2[t] = acc;
    }
    __syncthreads();
    if (t == 0) {
        float G3[NT3];
        for (int w = 0; w < NT3; w++) {
            int base = w * 16, end = min(base + 16, NT2);
            float acc = sG2[base];
            for (int i = base + 1; i < end; i++) acc = __fadd_rn(acc, sG2[i]);
            G3[w] = acc;
        }
        float acc = G3[0];
        sP4[0] = acc;
        for (int w = 1; w < NT3; w++) { acc = __fadd_rn(acc, G3[w]); sP4[w] = acc; }
    }
    __syncthreads();
    if (t < NT2) {
        int w = t >> 4, base = w * 16;
        float acc = sG2[base];
        for (int i = base + 1; i <= t; i++) acc = __fadd_rn(acc, sG2[i]);
        g_P3[b * NT2 + t] = (w > 0) ? __fadd_rn(sP4[w - 1], acc) : acc;
    }
}

// ---------------------------------------------------------------------------
// synth: 148 CTAs x 32 warps; warp = one chunk (10 or 11 tiles).
// Phase A: lanes 0..ntiles-1 run one tile scan each (exact op order) -> r.
// Phase B: 8-lane group/sample, 2 quads/iter, depth-1 register prefetch,
//          L2 prefetch 3 iterations ahead. Table in smem [512][68].
// ---------------------------------------------------------------------------
#define WT_STRIDE 68
#define SMEM_R_OFF (LWT_ * WT_STRIDE)                      // floats
#define MAIN_SMEM ((LWT_ * WT_STRIDE + 32 * MAX_SPW) * 4)  // 161792 B

__global__ void __launch_bounds__(1024, 1) synth_kernel(
    const float*  __restrict__ pitch,
    const float*  __restrict__ env,
    const float4* __restrict__ att4,      // [B*L][16] float4
    const float*  __restrict__ wt,        // [64][512]
    float*        __restrict__ out)
{
    extern __shared__ float s_wt[]; // [512][WT_STRIDE] then r[32][176]

    const int t    = threadIdx.x;
    const int lane = t & 31;
    const int wrp  = t >> 5;          // 32 warps/CTA
    for (int w = wrp; w < WW; w += 32) {
        const float4* row = (const float4*)(wt + w * LWT_);
        for (int c4 = lane; c4 < LWT_ / 4; c4 += 32) {
            float4 v = row[c4];
            int idx = c4 * 4;
            s_wt[(idx + 0) * WT_STRIDE + w] = v.x;
            s_wt[(idx + 1) * WT_STRIDE + w] = v.y;
            s_wt[(idx + 2) * WT_STRIDE + w] = v.z;
            s_wt[(idx + 3) * WT_STRIDE + w] = v.w;
        }
    }
    __syncthreads();

    const int gwarp = blockIdx.x * 32 + wrp;   // chunk id, < NCHUNKS
    const int b  = gwarp / CPR;
    const int k  = gwarp - b * CPR;
    const int first_tile = 10 * k + min(k, 40);
    const int ntiles = 10 + (k < 40 ? 1 : 0);
    const int s0 = b * LL + first_tile * 16;   // global first sample

    float* s_r = s_wt + SMEM_R_OFF + wrp * MAX_SPW;

    // -------- Phase A: per-tile scans (exact k3 op order) --------
    if (lane < ntiles) {
        const int i = first_tile + lane;
        const float* p  = pitch + b * LL + i * 16;
        const float* p0 = pitch + i * 16;            // batch row 0
        const float* G1 = g_G1 + b * NT1;

        float pref = 0.0f;
        bool has_pref = (i > 0);
        if (has_pref) {
            int j = i - 1, u = j >> 4, base = u * 16;
            float acc = G1[base];
            for (int kk = base + 1; kk <= j; kk++) acc = __fadd_rn(acc, G1[kk]);
            pref = (u > 0) ? __fadd_rn(g_P3[b * NT2 + (u - 1)], acc) : acc;
        }

        float acc = 0.0f;
        #pragma unroll
        for (int j = 0; j < 16; j++) {
            float leaf = __fmul_rn(K_INC, p[j]);
            acc = (j == 0) ? leaf : __fadd_rn(acc, leaf);
            float cum = has_pref ? __fadd_rn(pref, acc) : acc;
            float x = fmaf(-K_INC, p0[j], cum);  // XLA: sub(cum, mul) -> fma
            float r = fmodf(x, 512.0f);
            if (r < 0.0f) r = __fadd_rn(r, 512.0f);
            if (__fsub_rn(512.0f, r) < 1e-5f) r = 0.0f;
            s_r[lane * 16 + j] = r;
        }
    }
    __syncwarp();

    // -------- Phase B: pair-of-quads loop with prefetch --------
    const int grp = lane >> 3;             // sample within quad
    const int ls  = lane & 7;
    const int nq  = ntiles * 4;            // 40 or 44 (always even)

    float  e0_c, e1_c, r0_c, r1_c;
    float4 a00_c, a01_c, a10_c, a11_c;
    {
        int sA = s0 + grp, sB = s0 + 4 + grp;
        e0_c = env[sA];  e1_c = env[sB];
        r0_c = s_r[grp]; r1_c = s_r[4 + grp];
        const float4* apA = att4 + (size_t)sA * (WW / 4);
        const float4* apB = att4 + (size_t)sB * (WW / 4);
        a00_c = __ldcs(apA + ls);  a01_c = __ldcs(apA + ls + 8);
        a10_c = __ldcs(apB + ls);  a11_c = __ldcs(apB + ls + 8);
    }

    for (int q = 0; q < nq; q += 2) {
        // L2 prefetch 3 iterations ahead
        if (q + 6 < nq) {
            const float4* pfA = att4 + (size_t)(s0 + 4 * (q + 6) + grp) * (WW / 4);
            asm volatile("prefetch.global.L2 [%0];" :: "l"(pfA + ls));
            asm volatile("prefetch.global.L2 [%0];" :: "l"(pfA + ls + 8));
        }
        if (q + 7 < nq) {
            const float4* pfB = att4 + (size_t)(s0 + 4 * (q + 7) + grp) * (WW / 4);
            asm volatile("prefetch.global.L2 [%0];" :: "l"(pfB + ls));
            asm volatile("prefetch.global.L2 [%0];" :: "l"(pfB + ls + 8));
        }

        // register prefetch for next pair
        float  e0_n = 0.0f, e1_n = 0.0f, r0_n = 0.0f, r1_n = 0.0f;
        float4 a00_n = {}, a01_n = {}, a10_n = {}, a11_n = {};
        if (q + 2 < nq) {
            int sA = s0 + 4 * (q + 2) + grp, sB = s0 + 4 * (q + 3) + grp;
            e0_n = env[sA];  e1_n = env[sB];
            r0_n = s_r[4 * (q + 2) + grp]; r1_n = s_r[4 * (q + 3) + grp];
            const float4* apA = att4 + (size_t)sA * (WW / 4);
            const float4* apB = att4 + (size_t)sB * (WW / 4);
            a00_n = __ldcs(apA + ls);  a01_n = __ldcs(apA + ls + 8);
            a10_n = __ldcs(apB + ls);  a11_n = __ldcs(apB + ls + 8);
        }

        // --- stream 0 (quad q) ---
        float lowA = floorf(r0_c);
        float alA  = __fsub_rn(r0_c, lowA);
        int ilA = (int)lowA;
        int ihA = ((int)ceilf(r0_c)) & (LWT_ - 1);
        const float4* wlA = (const float4*)(s_wt + ilA * WT_STRIDE);
        const float4* whA = (const float4*)(s_wt + ihA * WT_STRIDE);
        float4 loA0 = wlA[ls], loA1 = wlA[ls + 8];
        float4 hiA0 = whA[ls], hiA1 = whA[ls + 8];

        // --- stream 1 (quad q+1) ---
        float lowB = floorf(r1_c);
        float alB  = __fsub_rn(r1_c, lowB);
        int ilB = (int)lowB;
        int ihB = ((int)ceilf(r1_c)) & (LWT_ - 1);
        const float4* wlB = (const float4*)(s_wt + ilB * WT_STRIDE);
        const float4* whB = (const float4*)(s_wt + ihB * WT_STRIDE);
        float4 loB0 = wlB[ls], loB1 = wlB[ls + 8];
        float4 hiB0 = whB[ls], hiB1 = whB[ls + 8];

        float accA;
        accA = a00_c.x * fmaf(alA, hiA0.x - loA0.x, loA0.x);
        accA = fmaf(a00_c.y, fmaf(alA, hiA0.y - loA0.y, loA0.y), accA);
        accA = fmaf(a00_c.z, fmaf(alA, hiA0.z - loA0.z, loA0.z), accA);
        accA = fmaf(a00_c.w, fmaf(alA, hiA0.w - loA0.w, loA0.w), accA);
        accA = fmaf(a01_c.x, fmaf(alA, hiA1.x - loA1.x, loA1.x), accA);
        accA = fmaf(a01_c.y, fmaf(alA, hiA1.y - loA1.y, loA1.y), accA);
        accA = fmaf(a01_c.z, fmaf(alA, hiA1.z - loA1.z, loA1.z), accA);
        accA = fmaf(a01_c.w, fmaf(alA, hiA1.w - loA1.w, loA1.w), accA);

        float accB;
        accB = a10_c.x * fmaf(alB, hiB0.x - loB0.x, loB0.x);
        accB = fmaf(a10_c.y, fmaf(alB, hiB0.y - loB0.y, loB0.y), accB);
        accB = fmaf(a10_c.z, fmaf(alB, hiB0.z - loB0.z, loB0.z), accB);
        accB = fmaf(a10_c.w, fmaf(alB, hiB0.w - loB0.w, loB0.w), accB);
        accB = fmaf(a11_c.x, fmaf(alB, hiB1.x - loB1.x, loB1.x), accB);
        accB = fmaf(a11_c.y, fmaf(alB, hiB1.y - loB1.y, loB1.y), accB);
        accB = fmaf(a11_c.z, fmaf(alB, hiB1.z - loB1.z, loB1.z), accB);
        accB = fmaf(a11_c.w, fmaf(alB, hiB1.w - loB1.w, loB1.w), accB);

        accA += __shfl_xor_sync(0xFFFFFFFFu, accA, 1);
        accB += __shfl_xor_sync(0xFFFFFFFFu, accB, 1);
        accA += __shfl_xor_sync(0xFFFFFFFFu, accA, 2);
        accB += __shfl_xor_sync(0xFFFFFFFFu, accB, 2);
        accA += __shfl_xor_sync(0xFFFFFFFFu, accA, 4);
        accB += __shfl_xor_sync(0xFFFFFFFFu, accB, 4);

        if (ls == 0) {
            out[s0 + 4 * q + grp]       = accA * e0_c;
            out[s0 + 4 * (q + 1) + grp] = accB * e1_c;
        }

        e0_c = e0_n; e1_c = e1_n; r0_c = r0_n; r1_c = r1_n;
        a00_c = a00_n; a01_c = a01_n; a10_c = a10_n; a11_c = a11_n;
    }
}

// ---------------------------------------------------------------------------
extern "C" void kernel_launch(void* const* d_in, const int* in_sizes, int n_in,
                              void* d_out, int out_size) {
    const float* pitch = (const float*)d_in[0];
    const float* env   = (const float*)d_in[1];
    const float* att   = (const float*)d_in[2];
    const float* wt    = (const float*)d_in[3];
    float* out         = (float*)d_out;

    cudaFuncSetAttribute(synth_kernel, cudaFuncAttributeMaxDynamicSharedMemorySize, MAIN_SMEM);

    scan_kernel<<<BB, 1024>>>(pitch);
    synth_kernel<<<NCHUNKS / 32, 1024, MAIN_SMEM>>>(pitch, env, (const float4*)att, wt, out);
}

// round 14
// speedup vs baseline: 1.7018x; 1.1147x over previous
#include <cuda_runtime.h>

// WavetableSynth: B=16, L=48000, W=64, LWT=512
// inputs: pitch (B*L f32), envelope (B*L f32), attention (B*L*W f32), wavetables (W*LWT f32)
// output: (B, L, 1) f32

#define BB 16
#define LL 48000
#define WW 64
#define LWT_ 512

static constexpr float K_INC = 512.0f / 16000.0f; // 0.032f in f32

#define NT1 3000   // 48000 / 16 tiles per row
#define NT2 188    // ceil(3000 / 16)
#define NT3 12     // ceil(188 / 16)

#define TPW 11                 // tiles per warp chunk
#define SPW (TPW * 16)         // 176 samples per chunk
#define CHUNKS_PER_ROW 273     // ceil(3000 / 11); last chunk = 8 tiles
#define NCHUNKS (BB * CHUNKS_PER_ROW)   // 4368

// scratch (referenced ONLY from device code)
__device__ float g_G1[BB * NT1];
__device__ float g_P3[BB * NT2];

// ---------------------------------------------------------------------------
// scan_kernel: fused G1/G2/G3/P4/P3, one CTA per batch row (16 CTAs x 1024).
// Exact XLA radix-16 op order.
// ---------------------------------------------------------------------------
__global__ void __launch_bounds__(1024, 1) scan_kernel(const float* __restrict__ pitch) {
    __shared__ float sG1[NT1];
    __shared__ float sG2[NT2], sP4[NT3];
    const int b = blockIdx.x;
    const int t = threadIdx.x;
    const float* p = pitch + b * LL;

    for (int i = t; i < NT1; i += 1024) {
        const float4* q = (const float4*)(p + i * 16);
        float4 v0 = q[0], v1 = q[1], v2 = q[2], v3 = q[3];
        float lv[16] = {v0.x,v0.y,v0.z,v0.w, v1.x,v1.y,v1.z,v1.w,
                        v2.x,v2.y,v2.z,v2.w, v3.x,v3.y,v3.z,v3.w};
        float acc = __fmul_rn(K_INC, lv[0]);
        #pragma unroll
        for (int j = 1; j < 16; j++) acc = __fadd_rn(acc, __fmul_rn(K_INC, lv[j]));
        sG1[i] = acc;
        g_G1[b * NT1 + i] = acc;
    }
    __syncthreads();

    if (t < NT2) {
        int base = t * 16, end = min(base + 16, NT1);
        float acc = sG1[base];
        for (int i = base + 1; i < end; i++) acc = __fadd_rn(acc, sG1[i]);
        sG2[t] = acc;
    }
    __syncthreads();
    if (t == 0) {
        float G3[NT3];
        for (int w = 0; w < NT3; w++) {
            int base = w * 16, end = min(base + 16, NT2);
            float acc = sG2[base];
            for (int i = base + 1; i < end; i++) acc = __fadd_rn(acc, sG2[i]);
            G3[w] = acc;
        }
        float acc = G3[0];
        sP4[0] = acc;
        for (int w = 1; w < NT3; w++) { acc = __fadd_rn(acc, G3[w]); sP4[w] = acc; }
    }
    __syncthreads();
    if (t < NT2) {
        int w = t >> 4, base = w * 16;
        float acc = sG2[base];
        for (int i = base + 1; i <= t; i++) acc = __fadd_rn(acc, sG2[i]);
        g_P3[b * NT2 + t] = (w > 0) ? __fadd_rn(sP4[w - 1], acc) : acc;
    }
}

// ---------------------------------------------------------------------------
// synth: VERBATIM round-11 configuration (measured ~45us): warp owns an
// 11-tile chunk; Phase A per-tile scans -> r in smem; Phase B 8-lane
// group/sample, 2 quads/iter, depth-1 register prefetch + L2 prefetch.
// ---------------------------------------------------------------------------
#define WT_STRIDE 68
#define SMEM_R_OFF (LWT_ * WT_STRIDE)                 // floats
#define MAIN_SMEM ((LWT_ * WT_STRIDE + 32 * SPW) * 4) // table + per-warp r

__global__ void __launch_bounds__(1024, 1) synth_kernel(
    const float*  __restrict__ pitch,
    const float*  __restrict__ env,
    const float4* __restrict__ att4,      // [B*L][16] float4
    const float*  __restrict__ wt,        // [64][512]
    float*        __restrict__ out)
{
    extern __shared__ float s_wt[]; // [512][WT_STRIDE] then r[32][176]

    const int t    = threadIdx.x;
    const int lane = t & 31;
    const int wrp  = t >> 5;          // 32 warps/CTA
    for (int w = wrp; w < WW; w += 32) {
        const float4* row = (const float4*)(wt + w * LWT_);
        for (int c4 = lane; c4 < LWT_ / 4; c4 += 32) {
            float4 v = row[c4];
            int idx = c4 * 4;
            s_wt[(idx + 0) * WT_STRIDE + w] = v.x;
            s_wt[(idx + 1) * WT_STRIDE + w] = v.y;
            s_wt[(idx + 2) * WT_STRIDE + w] = v.z;
            s_wt[(idx + 3) * WT_STRIDE + w] = v.w;
        }
    }
    __syncthreads();

    const int gwarp = blockIdx.x * 32 + wrp;   // chunk id
    if (gwarp >= NCHUNKS) return;

    const int b  = gwarp / CHUNKS_PER_ROW;
    const int k  = gwarp - b * CHUNKS_PER_ROW;
    const int first_tile = k * TPW;
    const int ntiles = min(TPW, NT1 - first_tile);
    const int s0 = b * LL + first_tile * 16;   // global first sample

    float* s_r = s_wt + SMEM_R_OFF + wrp * SPW;

    // -------- Phase A: per-tile scans --------
    if (lane < ntiles) {
        const int i = first_tile + lane;
        const float* p  = pitch + b * LL + i * 16;
        const float* p0 = pitch + i * 16;            // batch row 0
        const float* G1 = g_G1 + b * NT1;

        float pref = 0.0f;
        bool has_pref = (i > 0);
        if (has_pref) {
            int j = i - 1, u = j >> 4, base = u * 16;
            float acc = G1[base];
            for (int kk = base + 1; kk <= j; kk++) acc = __fadd_rn(acc, G1[kk]);
            pref = (u > 0) ? __fadd_rn(g_P3[b * NT2 + (u - 1)], acc) : acc;
        }

        float acc = 0.0f;
        #pragma unroll
        for (int j = 0; j < 16; j++) {
            float leaf = __fmul_rn(K_INC, p[j]);
            acc = (j == 0) ? leaf : __fadd_rn(acc, leaf);
            float cum = has_pref ? __fadd_rn(pref, acc) : acc;
            float x = fmaf(-K_INC, p0[j], cum);  // XLA: sub(cum, mul) -> fma
            float r = fmodf(x, 512.0f);
            if (r < 0.0f) r = __fadd_rn(r, 512.0f);
            if (__fsub_rn(512.0f, r) < 1e-5f) r = 0.0f;
            s_r[lane * 16 + j] = r;
        }
    }
    __syncwarp();

    // -------- Phase B: pair-of-quads loop with prefetch --------
    const int grp = lane >> 3;             // sample within quad
    const int ls  = lane & 7;
    const int nq  = ntiles * 4;            // 44 or 32 (always even)

    float  e0_c, e1_c, r0_c, r1_c;
    float4 a00_c, a01_c, a10_c, a11_c;
    {
        int sA = s0 + grp, sB = s0 + 4 + grp;
        e0_c = env[sA];  e1_c = env[sB];
        r0_c = s_r[grp]; r1_c = s_r[4 + grp];
        const float4* apA = att4 + (size_t)sA * (WW / 4);
        const float4* apB = att4 + (size_t)sB * (WW / 4);
        a00_c = __ldcs(apA + ls);  a01_c = __ldcs(apA + ls + 8);
        a10_c = __ldcs(apB + ls);  a11_c = __ldcs(apB + ls + 8);
    }

    for (int q = 0; q < nq; q += 2) {
        // L2 prefetch 3 iterations ahead (att only)
        if (q + 6 < nq) {
            const float4* pfA = att4 + (size_t)(s0 + 4 * (q + 6) + grp) * (WW / 4);
            asm volatile("prefetch.global.L2 [%0];" :: "l"(pfA + ls));
            asm volatile("prefetch.global.L2 [%0];" :: "l"(pfA + ls + 8));
        }
        if (q + 7 < nq) {
            const float4* pfB = att4 + (size_t)(s0 + 4 * (q + 7) + grp) * (WW / 4);
            asm volatile("prefetch.global.L2 [%0];" :: "l"(pfB + ls));
            asm volatile("prefetch.global.L2 [%0];" :: "l"(pfB + ls + 8));
        }

        // register prefetch for next pair
        float  e0_n = 0.0f, e1_n = 0.0f, r0_n = 0.0f, r1_n = 0.0f;
        float4 a00_n = {}, a01_n = {}, a10_n = {}, a11_n = {};
        if (q + 2 < nq) {
            int sA = s0 + 4 * (q + 2) + grp, sB = s0 + 4 * (q + 3) + grp;
            e0_n = env[sA];  e1_n = env[sB];
            r0_n = s_r[4 * (q + 2) + grp]; r1_n = s_r[4 * (q + 3) + grp];
            const float4* apA = att4 + (size_t)sA * (WW / 4);
            const float4* apB = att4 + (size_t)sB * (WW / 4);
            a00_n = __ldcs(apA + ls);  a01_n = __ldcs(apA + ls + 8);
            a10_n = __ldcs(apB + ls);  a11_n = __ldcs(apB + ls + 8);
        }

        // --- sample stream 0 (quad q) ---
        float lowA = floorf(r0_c);
        float alA  = __fsub_rn(r0_c, lowA);
        int ilA = (int)lowA;
        int ihA = ((int)ceilf(r0_c)) & (LWT_ - 1);
        const float4* wlA = (const float4*)(s_wt + ilA * WT_STRIDE);
        const float4* whA = (const float4*)(s_wt + ihA * WT_STRIDE);
        float4 loA0 = wlA[ls], loA1 = wlA[ls + 8];
        float4 hiA0 = whA[ls], hiA1 = whA[ls + 8];

        // --- sample stream 1 (quad q+1) ---
        float lowB = floorf(r1_c);
        float alB  = __fsub_rn(r1_c, lowB);
        int ilB = (int)lowB;
        int ihB = ((int)ceilf(r1_c)) & (LWT_ - 1);
        const float4* wlB = (const float4*)(s_wt + ilB * WT_STRIDE);
        const float4* whB = (const float4*)(s_wt + ihB * WT_STRIDE);
        float4 loB0 = wlB[ls], loB1 = wlB[ls + 8];
        float4 hiB0 = whB[ls], hiB1 = whB[ls + 8];

        float accA;
        accA = a00_c.x * fmaf(alA, hiA0.x - loA0.x, loA0.x);
        accA = fmaf(a00_c.y, fmaf(alA, hiA0.y - loA0.y, loA0.y), accA);
        accA = fmaf(a00_c.z, fmaf(alA, hiA0.z - loA0.z, loA0.z), accA);
        accA = fmaf(a00_c.w, fmaf(alA, hiA0.w - loA0.w, loA0.w), accA);
        accA = fmaf(a01_c.x, fmaf(alA, hiA1.x - loA1.x, loA1.x), accA);
        accA = fmaf(a01_c.y, fmaf(alA, hiA1.y - loA1.y, loA1.y), accA);
        accA = fmaf(a01_c.z, fmaf(alA, hiA1.z - loA1.z, loA1.z), accA);
        accA = fmaf(a01_c.w, fmaf(alA, hiA1.w - loA1.w, loA1.w), accA);

        float accB;
        accB = a10_c.x * fmaf(alB, hiB0.x - loB0.x, loB0.x);
        accB = fmaf(a10_c.y, fmaf(alB, hiB0.y - loB0.y, loB0.y), accB);
        accB = fmaf(a10_c.z, fmaf(alB, hiB0.z - loB0.z, loB0.z), accB);
        accB = fmaf(a10_c.w, fmaf(alB, hiB0.w - loB0.w, loB0.w), accB);
        accB = fmaf(a11_c.x, fmaf(alB, hiB1.x - loB1.x, loB1.x), accB);
        accB = fmaf(a11_c.y, fmaf(alB, hiB1.y - loB1.y, loB1.y), accB);
        accB = fmaf(a11_c.z, fmaf(alB, hiB1.z - loB1.z, loB1.z), accB);
        accB = fmaf(a11_c.w, fmaf(alB, hiB1.w - loB1.w, loB1.w), accB);

        accA += __shfl_xor_sync(0xFFFFFFFFu, accA, 1);
        accB += __shfl_xor_sync(0xFFFFFFFFu, accB, 1);
        accA += __shfl_xor_sync(0xFFFFFFFFu, accA, 2);
        accB += __shfl_xor_sync(0xFFFFFFFFu, accB, 2);
        accA += __shfl_xor_sync(0xFFFFFFFFu, accA, 4);
        accB += __shfl_xor_sync(0xFFFFFFFFu, accB, 4);

        if (ls == 0) {
            out[s0 + 4 * q + grp]       = accA * e0_c;
            out[s0 + 4 * (q + 1) + grp] = accB * e1_c;
        }

        e0_c = e0_n; e1_c = e1_n; r0_c = r0_n; r1_c = r1_n;
        a00_c = a00_n; a01_c = a01_n; a10_c = a10_n; a11_c = a11_n;
    }
}

// ---------------------------------------------------------------------------
extern "C" void kernel_launch(void* const* d_in, const int* in_sizes, int n_in,
                              void* d_out, int out_size) {
    const float* pitch = (const float*)d_in[0];
    const float* env   = (const float*)d_in[1];
    const float* att   = (const float*)d_in[2];
    const float* wt    = (const float*)d_in[3];
    float* out         = (float*)d_out;

    cudaFuncSetAttribute(synth_kernel, cudaFuncAttributeMaxDynamicSharedMemorySize, MAIN_SMEM);

    scan_kernel<<<BB, 1024>>>(pitch);
    synth_kernel<<<148, 1024, MAIN_SMEM>>>(pitch, env, (const float4*)att, wt, out);
}

// round 15
// speedup vs baseline: 1.7573x; 1.0326x over previous
#include <cuda_runtime.h>

// WavetableSynth: B=16, L=48000, W=64, LWT=512
// inputs: pitch (B*L f32), envelope (B*L f32), attention (B*L*W f32), wavetables (W*LWT f32)
// output: (B, L, 1) f32

#define BB 16
#define LL 48000
#define WW 64
#define LWT_ 512

static constexpr float K_INC = 512.0f / 16000.0f; // 0.032f in f32

#define NT1 3000   // 48000 / 16 tiles per row
#define NT2 188    // ceil(3000 / 16)
#define NT3 12     // ceil(188 / 16)

// warp = contiguous chunk of one row. 148 warps/row (40x21 + 108x20 tiles),
// 16 rows -> 2368 warps = 148 CTAs x 16 warps exactly.
#define WARPS_PER_ROW 148
#define MAX_TPW 21
#define MAX_SPW (MAX_TPW * 16)   // 336

// scratch (referenced ONLY from device code)
__device__ float g_G1[BB * NT1];
__device__ float g_P3[BB * NT2];

// ---------------------------------------------------------------------------
// scan_kernel: fused G1/G2/G3/P4/P3, one CTA per batch row (16 CTAs x 1024).
// Exact XLA radix-16 op order.
// ---------------------------------------------------------------------------
__global__ void __launch_bounds__(1024, 1) scan_kernel(const float* __restrict__ pitch) {
    __shared__ float sG1[NT1];
    __shared__ float sG2[NT2], sP4[NT3];
    const int b = blockIdx.x;
    const int t = threadIdx.x;
    const float* p = pitch + b * LL;

    for (int i = t; i < NT1; i += 1024) {
        const float4* q = (const float4*)(p + i * 16);
        float4 v0 = q[0], v1 = q[1], v2 = q[2], v3 = q[3];
        float lv[16] = {v0.x,v0.y,v0.z,v0.w, v1.x,v1.y,v1.z,v1.w,
                        v2.x,v2.y,v2.z,v2.w, v3.x,v3.y,v3.z,v3.w};
        float acc = __fmul_rn(K_INC, lv[0]);
        #pragma unroll
        for (int j = 1; j < 16; j++) acc = __fadd_rn(acc, __fmul_rn(K_INC, lv[j]));
        sG1[i] = acc;
        g_G1[b * NT1 + i] = acc;
    }
    __syncthreads();

    if (t < NT2) {
        int base = t * 16, end = min(base + 16, NT1);
        float acc = sG1[base];
        for (int i = base + 1; i < end; i++) acc = __fadd_rn(acc, sG1[i]);
        sG2[t] = acc;
    }
    __syncthreads();
    if (t == 0) {
        float G3[NT3];
        for (int w = 0; w < NT3; w++) {
            int base = w * 16, end = min(base + 16, NT2);
            float acc = sG2[base];
            for (int i = base + 1; i < end; i++) acc = __fadd_rn(acc, sG2[i]);
            G3[w] = acc;
        }
        float acc = G3[0];
        sP4[0] = acc;
        for (int w = 1; w < NT3; w++) { acc = __fadd_rn(acc, G3[w]); sP4[w] = acc; }
    }
    __syncthreads();
    if (t < NT2) {
        int w = t >> 4, base = w * 16;
        float acc = sG2[base];
        for (int i = base + 1; i <= t; i++) acc = __fadd_rn(acc, sG2[i]);
        g_P3[b * NT2 + t] = (w > 0) ? __fadd_rn(sP4[w - 1], acc) : acc;
    }
}

// ---------------------------------------------------------------------------
// synth: 148 CTAs x 512 threads (16 warps). 128-reg budget -> depth-2
// register prefetch of attention/env/r via a static 2-phase ping-pong
// (no rotation movs). Table in smem [512][68]; gathers conflict-free.
// ---------------------------------------------------------------------------
#define WT_STRIDE 68
#define SMEM_R_OFF (LWT_ * WT_STRIDE)                       // floats
#define MAIN_SMEM ((LWT_ * WT_STRIDE + 16 * MAX_SPW) * 4)   // 160768 B

struct Ctx { float4 a00, a01, a10, a11; float e0, e1, r0, r1; };

__device__ __forceinline__ void load_ctx(Ctx& c, const float* __restrict__ env,
                                         const float4* __restrict__ att4,
                                         const float* s_r, int s0, int q,
                                         int grp, int ls, bool pred) {
    if (pred) {
        int sA = s0 + 4 * q + grp, sB = s0 + 4 * (q + 1) + grp;
        c.e0 = env[sA];  c.e1 = env[sB];
        c.r0 = s_r[4 * q + grp]; c.r1 = s_r[4 * (q + 1) + grp];
        const float4* apA = att4 + (size_t)sA * (WW / 4);
        const float4* apB = att4 + (size_t)sB * (WW / 4);
        c.a00 = __ldcs(apA + ls);  c.a01 = __ldcs(apA + ls + 8);
        c.a10 = __ldcs(apB + ls);  c.a11 = __ldcs(apB + ls + 8);
    }
}

__device__ __forceinline__ void compute2(const Ctx& c, const float* s_wt,
                                         float* __restrict__ out,
                                         int s0, int q, int grp, int ls) {
    // stream 0 (quad q)
    float lowA = floorf(c.r0);
    float alA  = __fsub_rn(c.r0, lowA);
    int ilA = (int)lowA;
    int ihA = (ilA + 1) & (LWT_ - 1);        // == ceil path when alpha!=0; alpha==0 makes hi irrelevant
    const float4* wlA = (const float4*)(s_wt + ilA * WT_STRIDE);
    const float4* whA = (const float4*)(s_wt + ihA * WT_STRIDE);
    float4 loA0 = wlA[ls], loA1 = wlA[ls + 8];
    float4 hiA0 = whA[ls], hiA1 = whA[ls + 8];

    // stream 1 (quad q+1)
    float lowB = floorf(c.r1);
    float alB  = __fsub_rn(c.r1, lowB);
    int ilB = (int)lowB;
    int ihB = (ilB + 1) & (LWT_ - 1);
    const float4* wlB = (const float4*)(s_wt + ilB * WT_STRIDE);
    const float4* whB = (const float4*)(s_wt + ihB * WT_STRIDE);
    float4 loB0 = wlB[ls], loB1 = wlB[ls + 8];
    float4 hiB0 = whB[ls], hiB1 = whB[ls + 8];

    float accA;
    accA = c.a00.x * fmaf(alA, hiA0.x - loA0.x, loA0.x);
    accA = fmaf(c.a00.y, fmaf(alA, hiA0.y - loA0.y, loA0.y), accA);
    accA = fmaf(c.a00.z, fmaf(alA, hiA0.z - loA0.z, loA0.z), accA);
    accA = fmaf(c.a00.w, fmaf(alA, hiA0.w - loA0.w, loA0.w), accA);
    accA = fmaf(c.a01.x, fmaf(alA, hiA1.x - loA1.x, loA1.x), accA);
    accA = fmaf(c.a01.y, fmaf(alA, hiA1.y - loA1.y, loA1.y), accA);
    accA = fmaf(c.a01.z, fmaf(alA, hiA1.z - loA1.z, loA1.z), accA);
    accA = fmaf(c.a01.w, fmaf(alA, hiA1.w - loA1.w, loA1.w), accA);

    float accB;
    accB = c.a10.x * fmaf(alB, hiB0.x - loB0.x, loB0.x);
    accB = fmaf(c.a10.y, fmaf(alB, hiB0.y - loB0.y, loB0.y), accB);
    accB = fmaf(c.a10.z, fmaf(alB, hiB0.z - loB0.z, loB0.z), accB);
    accB = fmaf(c.a10.w, fmaf(alB, hiB0.w - loB0.w, loB0.w), accB);
    accB = fmaf(c.a11.x, fmaf(alB, hiB1.x - loB1.x, loB1.x), accB);
    accB = fmaf(c.a11.y, fmaf(alB, hiB1.y - loB1.y, loB1.y), accB);
    accB = fmaf(c.a11.z, fmaf(alB, hiB1.z - loB1.z, loB1.z), accB);
    accB = fmaf(c.a11.w, fmaf(alB, hiB1.w - loB1.w, loB1.w), accB);

    accA += __shfl_xor_sync(0xFFFFFFFFu, accA, 1);
    accB += __shfl_xor_sync(0xFFFFFFFFu, accB, 1);
    accA += __shfl_xor_sync(0xFFFFFFFFu, accA, 2);
    accB += __shfl_xor_sync(0xFFFFFFFFu, accB, 2);
    accA += __shfl_xor_sync(0xFFFFFFFFu, accA, 4);
    accB += __shfl_xor_sync(0xFFFFFFFFu, accB, 4);

    if (ls == 0) {
        out[s0 + 4 * q + grp]       = accA * c.e0;
        out[s0 + 4 * (q + 1) + grp] = accB * c.e1;
    }
}

__global__ void __launch_bounds__(512, 1) synth_kernel(
    const float*  __restrict__ pitch,
    const float*  __restrict__ env,
    const float4* __restrict__ att4,      // [B*L][16] float4
    const float*  __restrict__ wt,        // [64][512]
    float*        __restrict__ out)
{
    extern __shared__ float s_wt[]; // [512][WT_STRIDE] then r[16][336]

    const int t    = threadIdx.x;
    const int lane = t & 31;
    const int wrp  = t >> 5;          // 16 warps/CTA
    for (int w = wrp; w < WW; w += 16) {
        const float4* row = (const float4*)(wt + w * LWT_);
        for (int c4 = lane; c4 < LWT_ / 4; c4 += 32) {
            float4 v = row[c4];
            int idx = c4 * 4;
            s_wt[(idx + 0) * WT_STRIDE + w] = v.x;
            s_wt[(idx + 1) * WT_STRIDE + w] = v.y;
            s_wt[(idx + 2) * WT_STRIDE + w] = v.z;
            s_wt[(idx + 3) * WT_STRIDE + w] = v.w;
        }
    }
    __syncthreads();

    const int gwarp = blockIdx.x * 16 + wrp;     // 0..2367
    const int b = gwarp / WARPS_PER_ROW;
    const int k = gwarp - b * WARPS_PER_ROW;     // 0..147 within row
    const int first_tile = 20 * k + min(k, 40);
    const int ntiles = (k < 40) ? 21 : 20;
    const int s0 = b * LL + first_tile * 16;

    float* s_r = s_wt + SMEM_R_OFF + wrp * MAX_SPW;

    // -------- Phase A: per-tile scans (exact op order) --------
    if (lane < ntiles) {
        const int i = first_tile + lane;
        const float* p  = pitch + b * LL + i * 16;
        const float* p0 = pitch + i * 16;            // batch row 0
        const float* G1 = g_G1 + b * NT1;

        float pref = 0.0f;
        bool has_pref = (i > 0);
        if (has_pref) {
            int j = i - 1, u = j >> 4, base = u * 16;
            float acc = G1[base];
            for (int kk = base + 1; kk <= j; kk++) acc = __fadd_rn(acc, G1[kk]);
            pref = (u > 0) ? __fadd_rn(g_P3[b * NT2 + (u - 1)], acc) : acc;
        }

        float acc = 0.0f;
        #pragma unroll
        for (int j = 0; j < 16; j++) {
            float leaf = __fmul_rn(K_INC, p[j]);
            acc = (j == 0) ? leaf : __fadd_rn(acc, leaf);
            float cum = has_pref ? __fadd_rn(pref, acc) : acc;
            float x = fmaf(-K_INC, p0[j], cum);  // XLA: sub(cum, mul) -> fma
            float r = fmodf(x, 512.0f);
            if (r < 0.0f) r = __fadd_rn(r, 512.0f);
            if (__fsub_rn(512.0f, r) < 1e-5f) r = 0.0f;
            s_r[lane * 16 + j] = r;
        }
    }
    __syncwarp();

    // -------- Phase B: 2-phase ping-pong, depth-2 prefetch --------
    const int grp = lane >> 3;
    const int ls  = lane & 7;
    const int nq  = ntiles * 4;            // 80 or 84; % 4 == 0

    Ctx cE, cO;
    load_ctx(cE, env, att4, s_r, s0, 0, grp, ls, true);
    load_ctx(cO, env, att4, s_r, s0, 2, grp, ls, true);

    for (int q = 0; q < nq; q += 4) {
        const bool more = (q + 4 < nq);

        // L2 prefetch ~6 double-quads ahead
        if (q + 12 < nq) {
            const float4* pfA = att4 + (size_t)(s0 + 4 * (q + 12) + grp) * (WW / 4);
            const float4* pfB = att4 + (size_t)(s0 + 4 * (q + 13) + grp) * (WW / 4);
            asm volatile("prefetch.global.L2 [%0];" :: "l"(pfA + ls));
            asm volatile("prefetch.global.L2 [%0];" :: "l"(pfA + ls + 8));
            asm volatile("prefetch.global.L2 [%0];" :: "l"(pfB + ls));
            asm volatile("prefetch.global.L2 [%0];" :: "l"(pfB + ls + 8));
        }
        if (q + 14 < nq) {
            const float4* pfC = att4 + (size_t)(s0 + 4 * (q + 14) + grp) * (WW / 4);
            const float4* pfD = att4 + (size_t)(s0 + 4 * (q + 15) + grp) * (WW / 4);
            asm volatile("prefetch.global.L2 [%0];" :: "l"(pfC + ls));
            asm volatile("prefetch.global.L2 [%0];" :: "l"(pfC + ls + 8));
            asm volatile("prefetch.global.L2 [%0];" :: "l"(pfD + ls));
            asm volatile("prefetch.global.L2 [%0];" :: "l"(pfD + ls + 8));
        }

        // phase E: compute quads q,q+1; refill cE for q+4,q+5
        compute2(cE, s_wt, out, s0, q, grp, ls);
        load_ctx(cE, env, att4, s_r, s0, q + 4, grp, ls, more);

        // phase O: compute quads q+2,q+3; refill cO for q+6,q+7
        compute2(cO, s_wt, out, s0, q + 2, grp, ls);
        load_ctx(cO, env, att4, s_r, s0, q + 6, grp, ls, more);
    }
}

// ---------------------------------------------------------------------------
extern "C" void kernel_launch(void* const* d_in, const int* in_sizes, int n_in,
                              void* d_out, int out_size) {
    const float* pitch = (const float*)d_in[0];
    const float* env   = (const float*)d_in[1];
    const float* att   = (const float*)d_in[2];
    const float* wt    = (const float*)d_in[3];
    float* out         = (float*)d_out;

    cudaFuncSetAttribute(synth_kernel, cudaFuncAttributeMaxDynamicSharedMemorySize, MAIN_SMEM);

    scan_kernel<<<BB, 1024>>>(pitch);
    synth_kernel<<<148, 512, MAIN_SMEM>>>(pitch, env, (const float4*)att, wt, out);
}

// round 17
// speedup vs baseline: 1.9946x; 1.1351x over previous
#include <cuda_runtime.h>

// WavetableSynth: B=16, L=48000, W=64, LWT=512
// inputs: pitch (B*L f32), envelope (B*L f32), attention (B*L*W f32), wavetables (W*LWT f32)
// output: (B, L, 1) f32

#define BB 16
#define LL 48000
#define WW 64
#define LWT_ 512

static constexpr float K_INC = 512.0f / 16000.0f; // 0.032f in f32

#define NT1 3000   // 48000 / 16 tiles per row
#define NT2 188    // ceil(3000 / 16)
#define NT3 12     // ceil(188 / 16)

// warp = contiguous chunk of one row. 148 warps/row (40x21 + 108x20 tiles),
// 16 rows -> 2368 warps = 148 CTAs x 16 warps exactly.
#define WARPS_PER_ROW 148
#define MAX_TPW 21
#define MAX_SPW (MAX_TPW * 16)   // 336

// scratch (referenced ONLY from device code)
__device__ float g_G1[BB * NT1];
__device__ float g_P3[BB * NT2];

// ---------------------------------------------------------------------------
// scan_kernel: fused G1/G2/G3/P4/P3, one CTA per batch row (16 CTAs x 1024).
// Exact XLA radix-16 op order.
// ---------------------------------------------------------------------------
__global__ void __launch_bounds__(1024, 1) scan_kernel(const float* __restrict__ pitch) {
    __shared__ float sG1[NT1];
    __shared__ float sG2[NT2], sP4[NT3];
    const int b = blockIdx.x;
    const int t = threadIdx.x;
    const float* p = pitch + b * LL;

    for (int i = t; i < NT1; i += 1024) {
        const float4* q = (const float4*)(p + i * 16);
        float4 v0 = q[0], v1 = q[1], v2 = q[2], v3 = q[3];
        float lv[16] = {v0.x,v0.y,v0.z,v0.w, v1.x,v1.y,v1.z,v1.w,
                        v2.x,v2.y,v2.z,v2.w, v3.x,v3.y,v3.z,v3.w};
        float acc = __fmul_rn(K_INC, lv[0]);
        #pragma unroll
        for (int j = 1; j < 16; j++) acc = __fadd_rn(acc, __fmul_rn(K_INC, lv[j]));
        sG1[i] = acc;
        g_G1[b * NT1 + i] = acc;
    }
    __syncthreads();

    if (t < NT2) {
        int base = t * 16, end = min(base + 16, NT1);
        float acc = sG1[base];
        for (int i = base + 1; i < end; i++) acc = __fadd_rn(acc, sG1[i]);
        sG2[t] = acc;
    }
    __syncthreads();
    if (t == 0) {
        float G3[NT3];
        for (int w = 0; w < NT3; w++) {
            int base = w * 16, end = min(base + 16, NT2);
            float acc = sG2[base];
            for (int i = base + 1; i < end; i++) acc = __fadd_rn(acc, sG2[i]);
            G3[w] = acc;
        }
        float acc = G3[0];
        sP4[0] = acc;
        for (int w = 1; w < NT3; w++) { acc = __fadd_rn(acc, G3[w]); sP4[w] = acc; }
    }
    __syncthreads();
    if (t < NT2) {
        int w = t >> 4, base = w * 16;
        float acc = sG2[base];
        for (int i = base + 1; i <= t; i++) acc = __fadd_rn(acc, sG2[i]);
        g_P3[b * NT2 + t] = (w > 0) ? __fadd_rn(sP4[w - 1], acc) : acc;
    }
}

// ---------------------------------------------------------------------------
// synth: 148 CTAs x 512 threads. Table rows 64 floats (256B, 128B-aligned)
// with a float4-granular XOR swizzle: element (idx,w) at
// idx*64 + (w ^ 4*(idx&7)). Every 8-lane gather phase reads one aligned
// 128B window (minimum wavefronts, conflict-free); transpose store is
// 4-way conflicted but one-time.
// ---------------------------------------------------------------------------
#define WT_STRIDE 64
#define SMEM_R_OFF (LWT_ * WT_STRIDE)                       // floats
#define MAIN_SMEM ((LWT_ * WT_STRIDE + 16 * MAX_SPW) * 4)   // 152576 B

struct Ctx { float4 a00, a01, a10, a11; float e0, e1, r0, r1; };

__device__ __forceinline__ void load_ctx(Ctx& c, const float* __restrict__ env,
                                         const float4* __restrict__ att4,
                                         const float* s_r, int s0, int q,
                                         int grp, int ls, bool pred) {
    if (pred) {
        int sA = s0 + 4 * q + grp, sB = s0 + 4 * (q + 1) + grp;
        c.e0 = env[sA];  c.e1 = env[sB];
        c.r0 = s_r[4 * q + grp]; c.r1 = s_r[4 * (q + 1) + grp];
        const float4* apA = att4 + (size_t)sA * (WW / 4);
        const float4* apB = att4 + (size_t)sB * (WW / 4);
        c.a00 = __ldcs(apA + ls);  c.a01 = __ldcs(apA + ls + 8);
        c.a10 = __ldcs(apB + ls);  c.a11 = __ldcs(apB + ls + 8);
    }
}

__device__ __forceinline__ void compute2(const Ctx& c, const float* s_wt,
                                         float* __restrict__ out,
                                         int s0, int q, int grp, int ls) {
    // stream 0 (quad q)
    float lowA = floorf(c.r0);
    float alA  = __fsub_rn(c.r0, lowA);
    int ilA = (int)lowA;
    int ihA = (ilA + 1) & (LWT_ - 1);
    const float4* wlA = (const float4*)(s_wt + ilA * WT_STRIDE);
    const float4* whA = (const float4*)(s_wt + ihA * WT_STRIDE);
    int plA = ls ^ (ilA & 7), phA = ls ^ (ihA & 7);
    float4 loA0 = wlA[plA], loA1 = wlA[plA + 8];
    float4 hiA0 = whA[phA], hiA1 = whA[phA + 8];

    // stream 1 (quad q+1)
    float lowB = floorf(c.r1);
    float alB  = __fsub_rn(c.r1, lowB);
    int ilB = (int)lowB;
    int ihB = (ilB + 1) & (LWT_ - 1);
    const float4* wlB = (const float4*)(s_wt + ilB * WT_STRIDE);
    const float4* whB = (const float4*)(s_wt + ihB * WT_STRIDE);
    int plB = ls ^ (ilB & 7), phB = ls ^ (ihB & 7);
    float4 loB0 = wlB[plB], loB1 = wlB[plB + 8];
    float4 hiB0 = whB[phB], hiB1 = whB[phB + 8];

    float accA;
    accA = c.a00.x * fmaf(alA, hiA0.x - loA0.x, loA0.x);
    accA = fmaf(c.a00.y, fmaf(alA, hiA0.y - loA0.y, loA0.y), accA);
    accA = fmaf(c.a00.z, fmaf(alA, hiA0.z - loA0.z, loA0.z), accA);
    accA = fmaf(c.a00.w, fmaf(alA, hiA0.w - loA0.w, loA0.w), accA);
    accA = fmaf(c.a01.x, fmaf(alA, hiA1.x - loA1.x, loA1.x), accA);
    accA = fmaf(c.a01.y, fmaf(alA, hiA1.y - loA1.y, loA1.y), accA);
    accA = fmaf(c.a01.z, fmaf(alA, hiA1.z - loA1.z, loA1.z), accA);
    accA = fmaf(c.a01.w, fmaf(alA, hiA1.w - loA1.w, loA1.w), accA);

    float accB;
    accB = c.a10.x * fmaf(alB, hiB0.x - loB0.x, loB0.x);
    accB = fmaf(c.a10.y, fmaf(alB, hiB0.y - loB0.y, loB0.y), accB);
    accB = fmaf(c.a10.z, fmaf(alB, hiB0.z - loB0.z, loB0.z), accB);
    accB = fmaf(c.a10.w, fmaf(alB, hiB0.w - loB0.w, loB0.w), accB);
    accB = fmaf(c.a11.x, fmaf(alB, hiB1.x - loB1.x, loB1.x), accB);
    accB = fmaf(c.a11.y, fmaf(alB, hiB1.y - loB1.y, loB1.y), accB);
    accB = fmaf(c.a11.z, fmaf(alB, hiB1.z - loB1.z, loB1.z), accB);
    accB = fmaf(c.a11.w, fmaf(alB, hiB1.w - loB1.w, loB1.w), accB);

    accA += __shfl_xor_sync(0xFFFFFFFFu, accA, 1);
    accB += __shfl_xor_sync(0xFFFFFFFFu, accB, 1);
    accA += __shfl_xor_sync(0xFFFFFFFFu, accA, 2);
    accB += __shfl_xor_sync(0xFFFFFFFFu, accB, 2);
    accA += __shfl_xor_sync(0xFFFFFFFFu, accA, 4);
    accB += __shfl_xor_sync(0xFFFFFFFFu, accB, 4);

    if (ls == 0) {
        out[s0 + 4 * q + grp]       = accA * c.e0;
        out[s0 + 4 * (q + 1) + grp] = accB * c.e1;
    }
}

__global__ void __launch_bounds__(512, 1) synth_kernel(
    const float*  __restrict__ pitch,
    const float*  __restrict__ env,
    const float4* __restrict__ att4,      // [B*L][16] float4
    const float*  __restrict__ wt,        // [64][512]
    float*        __restrict__ out)
{
    extern __shared__ float s_wt[]; // [512][64] swizzled, then r[16][336]

    const int t    = threadIdx.x;
    const int lane = t & 31;
    const int wrp  = t >> 5;          // 16 warps/CTA

    // transpose+swizzle: warp wrp owns idx block [32*wrp, 32*wrp+32).
    // lane ln handles idx = i0+ln; loop w: coalesced LDG, 4-way-conflict STS.
    {
        const int i0  = wrp * 32;
        const int idx = i0 + lane;
        const int sw  = 4 * (idx & 7);
        float* dst = s_wt + idx * WT_STRIDE;
        #pragma unroll 8
        for (int w = 0; w < WW; w++) {
            dst[w ^ sw] = wt[w * LWT_ + idx];
        }
    }
    __syncthreads();

    const int gwarp = blockIdx.x * 16 + wrp;     // 0..2367
    const int b = gwarp / WARPS_PER_ROW;
    const int k = gwarp - b * WARPS_PER_ROW;     // 0..147 within row
    const int first_tile = 20 * k + min(k, 40);
    const int ntiles = (k < 40) ? 21 : 20;
    const int s0 = b * LL + first_tile * 16;

    float* s_r = s_wt + SMEM_R_OFF + wrp * MAX_SPW;

    // -------- Phase A: per-tile scans (exact op order) --------
    if (lane < ntiles) {
        const int i = first_tile + lane;
        const float* p  = pitch + b * LL + i * 16;
        const float* p0 = pitch + i * 16;            // batch row 0
        const float* G1 = g_G1 + b * NT1;

        float pref = 0.0f;
        bool has_pref = (i > 0);
        if (has_pref) {
            int j = i - 1, u = j >> 4, base = u * 16;
            float acc = G1[base];
            for (int kk = base + 1; kk <= j; kk++) acc = __fadd_rn(acc, G1[kk]);
            pref = (u > 0) ? __fadd_rn(g_P3[b * NT2 + (u - 1)], acc) : acc;
        }

        float acc = 0.0f;
        #pragma unroll
        for (int j = 0; j < 16; j++) {
            float leaf = __fmul_rn(K_INC, p[j]);
            acc = (j == 0) ? leaf : __fadd_rn(acc, leaf);
            float cum = has_pref ? __fadd_rn(pref, acc) : acc;
            float x = fmaf(-K_INC, p0[j], cum);  // XLA: sub(cum, mul) -> fma
            float r = fmodf(x, 512.0f);
            if (r < 0.0f) r = __fadd_rn(r, 512.0f);
            if (__fsub_rn(512.0f, r) < 1e-5f) r = 0.0f;
            s_r[lane * 16 + j] = r;
        }
    }
    __syncwarp();

    // -------- Phase B: 2-phase ping-pong, depth-2 prefetch --------
    const int grp = lane >> 3;
    const int ls  = lane & 7;
    const int nq  = ntiles * 4;            // 80 or 84; % 4 == 0

    Ctx cE, cO;
    load_ctx(cE, env, att4, s_r, s0, 0, grp, ls, true);
    load_ctx(cO, env, att4, s_r, s0, 2, grp, ls, true);

    for (int q = 0; q < nq; q += 4) {
        const bool more = (q + 4 < nq);

        // L2 prefetch ~3 double-quads ahead
        if (q + 12 < nq) {
            const float4* pfA = att4 + (size_t)(s0 + 4 * (q + 12) + grp) * (WW / 4);
            const float4* pfB = att4 + (size_t)(s0 + 4 * (q + 13) + grp) * (WW / 4);
            asm volatile("prefetch.global.L2 [%0];" :: "l"(pfA + ls));
            asm volatile("prefetch.global.L2 [%0];" :: "l"(pfA + ls + 8));
            asm volatile("prefetch.global.L2 [%0];" :: "l"(pfB + ls));
            asm volatile("prefetch.global.L2 [%0];" :: "l"(pfB + ls + 8));
        }
        if (q + 14 < nq) {
            const float4* pfC = att4 + (size_t)(s0 + 4 * (q + 14) + grp) * (WW / 4);
            const float4* pfD = att4 + (size_t)(s0 + 4 * (q + 15) + grp) * (WW / 4);
            asm volatile("prefetch.global.L2 [%0];" :: "l"(pfC + ls));
            asm volatile("prefetch.global.L2 [%0];" :: "l"(pfC + ls + 8));
            asm volatile("prefetch.global.L2 [%0];" :: "l"(pfD + ls));
            asm volatile("prefetch.global.L2 [%0];" :: "l"(pfD + ls + 8));
        }

        // phase E: compute quads q,q+1; refill cE for q+4,q+5
        compute2(cE, s_wt, out, s0, q, grp, ls);
        load_ctx(cE, env, att4, s_r, s0, q + 4, grp, ls, more);

        // phase O: compute quads q+2,q+3; refill cO for q+6,q+7
        compute2(cO, s_wt, out, s0, q + 2, grp, ls);
        load_ctx(cO, env, att4, s_r, s0, q + 6, grp, ls, more);
    }
}

// ---------------------------------------------------------------------------
extern "C" void kernel_launch(void* const* d_in, const int* in_sizes, int n_in,
                              void* d_out, int out_size) {
    const float* pitch = (const float*)d_in[0];
    const float* env   = (const float*)d_in[1];
    const float* att   = (const float*)d_in[2];
    const float* wt    = (const float*)d_in[3];
    float* out         = (float*)d_out;

    cudaFuncSetAttribute(synth_kernel, cudaFuncAttributeMaxDynamicSharedMemorySize, MAIN_SMEM);

    scan_kernel<<<BB, 1024>>>(pitch);
    synth_kernel<<<148, 512, MAIN_SMEM>>>(pitch, env, (const float4*)att, wt, out);
}